// round 10
// baseline (speedup 1.0000x reference)
#include <cuda_runtime.h>
#include <cuda_bf16.h>
#include <math.h>

// Problem shapes (fixed by the dataset)
#define BDIM 8
#define NDIM 8192
#define CDIM 256
#define HDIM 256
#define ODIM 256
#define KDIM 64
#define CONC 512
#define LEAKY_ALPHA 0.3f
#define EPS 1e-6f

#define HT 16               // h-slice width per compute block
#define NHT (HDIM / HT)     // 16
#define ROUND 32            // neighbors per round
#define NCOMPUTE (NHT * BDIM)  // 128 compute blocks
#define NGEMV 8             // gemv blocks (o-tiles of 32)
#define CS_PAD 516          // padded concat row (conflict-free bb-split reads)

// Global scratch / sync (no allocation)
__device__ float g_wsh[BDIM * HDIM];     // final weighted-sum hidden (already divided)
__device__ float g_hidden[BDIM * ODIM];  // pre-norm hidden
__device__ float g_ssq[BDIM * NGEMV];    // per-(b, o-block) sum of squares
__device__ int   g_done   = 0;           // compute-block completion counter
__device__ int   g_arrive = 0;           // gemv-block arrival counter

__device__ __forceinline__ float leaky(float x) {
    return x >= 0.0f ? x : LEAKY_ALPHA * x;
}

__global__ void __launch_bounds__(1024, 1)
fused_convolve(const float* __restrict__ emb,
               const float* __restrict__ weights,
               const float* __restrict__ Qw,
               const float* __restrict__ Qb,
               const float* __restrict__ Ww,
               const float* __restrict__ Wb,
               const int*   __restrict__ nb,
               const int*   __restrict__ nid_p,
               float*       __restrict__ out)
{
    // Union: compute role uses embs[32][257] (8224 f) with redbuf[8][32][4]f4
    // aliased at offset 0 (16KB, lifetime disjoint via barriers).
    // gemv role uses cs[8][516] (4128 f) + red[16][64]f4 (4096 f) + sq[64].
    __shared__ __align__(16) float smem[8352];
    __shared__ int   s_flag;
    __shared__ float s_misc[12];

    const int bid = blockIdx.x;
    const int tid = threadIdx.x;
    const int nid = *nid_p;

    if (bid < NCOMPUTE) {
        // ================= COMPUTE ROLE =================
        // block owns (h-tile ht, batch b); processes all 64 neighbors in 2 rounds.
        const int ht = bid >> 3;     // 0..15
        const int b  = bid & 7;      // 0..7

        float*  embs   = smem;              // [32][257] floats (pad -> conflict-free)
        float4* redbuf = (float4*)smem;     // alias, [cs 8][k 32][h4 4]

        const int k   = tid & 31;           // neighbor-in-round
        const int h4  = (tid >> 5) & 3;     // which float4 of the 16-h slice
        const int cs  = tid >> 7;           // c-split 0..7 (32 c each)
        const int cb  = cs * 32;
        const int qcol = ht * 4 + h4;       // float4 column in Qw row
        const float4* Qw4 = (const float4*)Qw;

        float4 hacc = make_float4(0.f, 0.f, 0.f, 0.f);  // running h-sums (warps 0-3)
        float  wacc = 0.f;                               // running weight sum (warp 0)

        for (int r = 0; r < 2; r++) {
            __syncthreads();   // prior-round redbuf reads done before embs overwrite

            // Stage 32 neighbor rows into embs[row][c] (stride 257).
            // Coalesced float4 global reads; scalar STS (pad keeps loop LDS conflict-free).
            for (int f = tid; f < 2048; f += 1024) {
                int row = f >> 6, c4 = f & 63;
                int n = __ldg(&nb[r * ROUND + row]);
                float4 v = *(const float4*)(emb + ((size_t)(b * NDIM + n)) * CDIM + c4 * 4);
                float* d = embs + row * 257 + c4 * 4;
                d[0] = v.x; d[1] = v.y; d[2] = v.z; d[3] = v.w;
            }
            __syncthreads();

            // Hot loop: e from smem (conflict-free), q broadcast LDG (16KB, L1-resident)
            float4 acc = make_float4(0.f, 0.f, 0.f, 0.f);
            const float* erow = embs + k * 257;
            #pragma unroll 8
            for (int i = 0; i < 32; i++) {
                int c = cb + i;
                float  e = erow[c];
                float4 q = __ldg(&Qw4[c * 64 + qcol]);
                acc.x = fmaf(e, q.x, acc.x);
                acc.y = fmaf(e, q.y, acc.y);
                acc.z = fmaf(e, q.z, acc.z);
                acc.w = fmaf(e, q.w, acc.w);
            }
            __syncthreads();   // all embs reads done before redbuf alias write
            redbuf[cs * 128 + k * 4 + h4] = acc;
            __syncthreads();

            // Reduce over the 8 c-splits, bias+leaky+weight, then sum over k.
            if (tid < 128) {   // warps 0-3 exactly (full warps -> shuffles safe)
                float4 d = redbuf[k * 4 + h4];
                #pragma unroll
                for (int c2 = 1; c2 < 8; c2++) {
                    float4 p = redbuf[c2 * 128 + k * 4 + h4];
                    d.x += p.x; d.y += p.y; d.z += p.z; d.w += p.w;
                }
                float4 qb = __ldg(((const float4*)Qb) + qcol);
                int    n  = __ldg(&nb[r * ROUND + k]);
                float  w  = __ldg(&weights[(size_t)n * NDIM + nid]);
                float4 val;
                val.x = leaky(d.x + qb.x) * w;
                val.y = leaky(d.y + qb.y) * w;
                val.z = leaky(d.z + qb.z) * w;
                val.w = leaky(d.w + qb.w) * w;
                #pragma unroll
                for (int off = 16; off > 0; off >>= 1) {
                    val.x += __shfl_xor_sync(0xFFFFFFFFu, val.x, off);
                    val.y += __shfl_xor_sync(0xFFFFFFFFu, val.y, off);
                    val.z += __shfl_xor_sync(0xFFFFFFFFu, val.z, off);
                    val.w += __shfl_xor_sync(0xFFFFFFFFu, val.w, off);
                }
                hacc.x += val.x; hacc.y += val.y; hacc.z += val.z; hacc.w += val.w;
                if (h4 == 0) {   // warp 0 (full) accumulates weight sum
                    float ww = w;
                    #pragma unroll
                    for (int off = 16; off > 0; off >>= 1)
                        ww += __shfl_xor_sync(0xFFFFFFFFu, ww, off);
                    wacc += ww;
                }
            }
        }

        __syncthreads();
        if (tid == 0) s_misc[8] = wacc;   // broadcast weight sum
        __syncthreads();
        if (tid < 128 && (tid & 31) == 0) {
            const int h4e = tid >> 5;
            float inv = 1.0f / (s_misc[8] + EPS);
            float4 o;
            o.x = hacc.x * inv; o.y = hacc.y * inv;
            o.z = hacc.z * inv; o.w = hacc.w * inv;
            *(float4*)(g_wsh + b * HDIM + ht * HT + h4e * 4) = o;
        }
        __threadfence();
        __syncthreads();
        if (tid == 0) atomicAdd(&g_done, 1);
    } else {
        // ================= GEMV ROLE =================
        const int ob = bid - NCOMPUTE;   // o-tile 0..7 (32 outputs)

        float*  cs_s = smem;                          // [8][CS_PAD]
        float4* red  = (float4*)(smem + 8 * CS_PAD);  // [cq 16][bb*8+og 64]
        float*  sq   = smem + 8 * CS_PAD + 4096;      // [64]

        // Pre-gate: node embeddings (independent of compute blocks) -> overlap
        if (tid < 512) {
            int bn = tid >> 6, col = tid & 63;
            float4 v = *(const float4*)(emb + ((size_t)(bn * NDIM + nid)) * CDIM + col * 4);
            *(float4*)(cs_s + bn * CS_PAD + col * 4) = v;
        }

        // Gate on compute completion
        if (tid == 0) {
            while (atomicAdd(&g_done, 0) < NCOMPUTE) __nanosleep(64);
            s_flag = 1;
        }
        __syncthreads();
        __threadfence();

        if (tid < 512) {
            int bn = tid >> 6, col = tid & 63;
            float4 v = __ldcg(((const float4*)(g_wsh + bn * HDIM)) + col);
            *(float4*)(cs_s + bn * CS_PAD + CDIM + col * 4) = v;
        }
        __syncthreads();

        // GEMV: o-tile for all 8 batches; warp lanes (og 8 x bb 4) -> 1 line/warp-LDG
        const int og = tid & 7;
        const int bb = (tid >> 3) & 7;
        const int cq = tid >> 6;
        const float4* Ww4 = (const float4*)Ww;
        const float*  e   = cs_s + bb * CS_PAD;

        float4 acc = make_float4(0.f, 0.f, 0.f, 0.f);
        #pragma unroll 8
        for (int c = cq * 32; c < cq * 32 + 32; c++) {
            float  ev = e[c];
            float4 q  = __ldg(&Ww4[c * 64 + ob * 8 + og]);
            acc.x = fmaf(ev, q.x, acc.x);
            acc.y = fmaf(ev, q.y, acc.y);
            acc.z = fmaf(ev, q.z, acc.z);
            acc.w = fmaf(ev, q.w, acc.w);
        }
        red[cq * 64 + bb * 8 + og] = acc;
        __syncthreads();

        if (tid < 64) {
            const int b2 = tid >> 3, og2 = tid & 7;
            float4 s = red[tid];
            #pragma unroll
            for (int i = 1; i < 16; i++) {
                float4 rr = red[i * 64 + tid];
                s.x += rr.x; s.y += rr.y; s.z += rr.z; s.w += rr.w;
            }
            float4 wb = ((const float4*)Wb)[ob * 8 + og2];
            float4 v;
            v.x = leaky(s.x + wb.x);
            v.y = leaky(s.y + wb.y);
            v.z = leaky(s.z + wb.z);
            v.w = leaky(s.w + wb.w);
            *(float4*)(g_hidden + (size_t)b2 * ODIM + ob * 32 + og2 * 4) = v;
            sq[tid] = v.x*v.x + v.y*v.y + v.z*v.z + v.w*v.w;
        }
        __syncthreads();
        if (tid < 8) {
            float t = 0.f;
            #pragma unroll
            for (int i = 0; i < 8; i++) t += sq[tid * 8 + i];
            g_ssq[tid * NGEMV + ob] = t;
        }
        __threadfence();
        __syncthreads();
        if (tid == 0) s_flag = (atomicAdd(&g_arrive, 1) == NGEMV - 1);
        __syncthreads();

        if (s_flag) {
            // Last-arriving gemv block: normalize + store + reset counters.
            __threadfence();
            if (tid < 8) {
                float t = 0.f;
                #pragma unroll
                for (int i = 0; i < 8; i++) t += __ldcg(&g_ssq[tid * NGEMV + i]);
                s_misc[tid] = 1.0f / (sqrtf(t) + EPS);
            }
            __syncthreads();
            if (tid < 512) {
                int bn = tid >> 6, o4 = tid & 63;
                float4 v = __ldcg(((const float4*)(g_hidden + (size_t)bn * ODIM)) + o4);
                float iv = s_misc[bn];
                v.x *= iv; v.y *= iv; v.z *= iv; v.w *= iv;
                *(float4*)(out + (size_t)bn * ODIM + o4 * 4) = v;
            }
            if (tid == 0) { g_done = 0; g_arrive = 0; }
        }
    }
}

extern "C" void kernel_launch(void* const* d_in, const int* in_sizes, int n_in,
                              void* d_out, int out_size)
{
    (void)in_sizes; (void)n_in; (void)out_size;
    const float* emb     = (const float*)d_in[0];
    const float* weights = (const float*)d_in[1];
    const float* Qw      = (const float*)d_in[2];
    const float* Qb      = (const float*)d_in[3];
    const float* Ww      = (const float*)d_in[4];
    const float* Wb      = (const float*)d_in[5];
    const int*   nb      = (const int*)d_in[6];
    const int*   nid     = (const int*)d_in[7];
    float*       out     = (float*)d_out;

    fused_convolve<<<NCOMPUTE + NGEMV, 1024>>>(emb, weights, Qw, Qb, Ww, Wb, nb, nid, out);
}

// round 11
// speedup vs baseline: 1.2694x; 1.2694x over previous
#include <cuda_runtime.h>
#include <cuda_bf16.h>
#include <math.h>

// Problem shapes (fixed by the dataset)
#define BDIM 8
#define NDIM 8192
#define CDIM 256
#define HDIM 256
#define ODIM 256
#define KDIM 64
#define KCHUNK 4
#define NCHUNKS (KDIM / KCHUNK)   // 16
#define NCOMPUTE (NCHUNKS * BDIM) // 128 compute blocks
#define NGEMV 8                   // gemv blocks (o-tiles of 32)
#define CONC (CDIM + HDIM)        // 512
#define CS_PAD 516                // padded concat row (conflict-free bb-split)
#define LEAKY_ALPHA 0.3f
#define EPS 1e-6f

// Global scratch / sync (no allocation)
__device__ float g_partial[BDIM * NCHUNKS * HDIM];  // per-(b,chunk) weighted hidden sums
__device__ float g_wsum[BDIM * NCHUNKS];            // per-(b,chunk) neighbor-weight sums
__device__ float g_hidden[BDIM * ODIM];             // pre-norm hidden
__device__ float g_ssq[BDIM * NGEMV];               // per-(b, o-block) sum of squares
__device__ int   g_done   = 0;                      // compute completion counter
__device__ int   g_arrive = 0;                      // gemv arrival counter

__device__ __forceinline__ float leaky(float x) {
    return x >= 0.0f ? x : LEAKY_ALPHA * x;
}

__global__ void __launch_bounds__(1024, 1)
fused_convolve(const float* __restrict__ emb,
               const float* __restrict__ weights,
               const float* __restrict__ Qw,
               const float* __restrict__ Qb,
               const float* __restrict__ Ww,
               const float* __restrict__ Wb,
               const int*   __restrict__ nb,
               const int*   __restrict__ nid_p,
               float*       __restrict__ out)
{
    // Shared memory, carved per role (max 36.9 KB, static).
    __shared__ __align__(16) unsigned char smem_raw[37376];
    __shared__ float s_misc[12];

    const int bid = blockIdx.x;
    const int tid = threadIdx.x;
    const int nid = *nid_p;

    if (bid < NCOMPUTE) {
        // ================= COMPUTE ROLE (R8 k1, verbatim body) =================
        const int chunk = bid >> 3;   // 0..15
        const int b     = bid & 7;    // 0..7
        const int th    = tid & 63;   // h-group (float4 on Qw rows)
        const int tc    = tid >> 6;   // c-chunk 0..15 (16 c each)

        float4* part8 = (float4*)smem_raw;                    // [8][KCHUNK][64] = 32 KB
        float*  embs  = (float*)(smem_raw + 32768);           // [KCHUNK][256]  = 4 KB
        float*  ws    = (float*)(smem_raw + 36864);           // [4]
        int*    nbs   = (int*)  (smem_raw + 36880);           // [4]

        const int c0  = tc * 16;
        const float4* Qw4 = (const float4*)Qw;

        // Prefetch first 4 Qw vectors (independent of nb/emb prologue)
        float4 q0 = __ldg(&Qw4[(c0 + 0) * 64 + th]);
        float4 q1 = __ldg(&Qw4[(c0 + 1) * 64 + th]);
        float4 q2 = __ldg(&Qw4[(c0 + 2) * 64 + th]);
        float4 q3 = __ldg(&Qw4[(c0 + 3) * 64 + th]);

        if (tid < KCHUNK) {
            int n = nb[chunk * KCHUNK + tid];
            nbs[tid] = n;
            ws[tid] = weights[(size_t)n * NDIM + nid];
        }
        __syncthreads();

        if (tid < 256) {
            int r = tid >> 6, col = tid & 63;
            ((float4*)(embs + r * CDIM))[col] =
                ((const float4*)(emb + ((size_t)b * NDIM + nbs[r]) * CDIM))[col];
        }
        __syncthreads();

        float4 a0 = make_float4(0.f,0.f,0.f,0.f);
        float4 a1 = make_float4(0.f,0.f,0.f,0.f);
        float4 a2 = make_float4(0.f,0.f,0.f,0.f);
        float4 a3 = make_float4(0.f,0.f,0.f,0.f);

        {
            float e0, e1, e2, e3;
            #define K1_FMA(Q, CI)                                                       \
                e0 = embs[0*CDIM + (CI)]; e1 = embs[1*CDIM + (CI)];                     \
                e2 = embs[2*CDIM + (CI)]; e3 = embs[3*CDIM + (CI)];                     \
                a0.x = fmaf(e0,(Q).x,a0.x); a0.y = fmaf(e0,(Q).y,a0.y);                 \
                a0.z = fmaf(e0,(Q).z,a0.z); a0.w = fmaf(e0,(Q).w,a0.w);                 \
                a1.x = fmaf(e1,(Q).x,a1.x); a1.y = fmaf(e1,(Q).y,a1.y);                 \
                a1.z = fmaf(e1,(Q).z,a1.z); a1.w = fmaf(e1,(Q).w,a1.w);                 \
                a2.x = fmaf(e2,(Q).x,a2.x); a2.y = fmaf(e2,(Q).y,a2.y);                 \
                a2.z = fmaf(e2,(Q).z,a2.z); a2.w = fmaf(e2,(Q).w,a2.w);                 \
                a3.x = fmaf(e3,(Q).x,a3.x); a3.y = fmaf(e3,(Q).y,a3.y);                 \
                a3.z = fmaf(e3,(Q).z,a3.z); a3.w = fmaf(e3,(Q).w,a3.w)

            K1_FMA(q0, c0 + 0);
            K1_FMA(q1, c0 + 1);
            K1_FMA(q2, c0 + 2);
            K1_FMA(q3, c0 + 3);

            #pragma unroll
            for (int i = 4; i < 16; i++) {
                float4 q = __ldg(&Qw4[(c0 + i) * 64 + th]);
                K1_FMA(q, c0 + i);
            }
            #undef K1_FMA
        }

        // Two-round c-chunk combine (16 chunks through the 8-slot buffer)
        #define P8(s,k,h) part8[((s) * KCHUNK + (k)) * 64 + (h)]
        if (tc >= 8) {
            P8(tc-8,0,th) = a0; P8(tc-8,1,th) = a1;
            P8(tc-8,2,th) = a2; P8(tc-8,3,th) = a3;
        }
        __syncthreads();
        if (tc < 8) {
            float4 p;
            p = P8(tc,0,th); a0.x += p.x; a0.y += p.y; a0.z += p.z; a0.w += p.w;
            p = P8(tc,1,th); a1.x += p.x; a1.y += p.y; a1.z += p.z; a1.w += p.w;
            p = P8(tc,2,th); a2.x += p.x; a2.y += p.y; a2.z += p.z; a2.w += p.w;
            p = P8(tc,3,th); a3.x += p.x; a3.y += p.y; a3.z += p.z; a3.w += p.w;
        }
        __syncthreads();
        if (tc < 8) {
            P8(tc,0,th) = a0; P8(tc,1,th) = a1;
            P8(tc,2,th) = a2; P8(tc,3,th) = a3;
        }
        __syncthreads();

        if (tid < 256) {
            int k = tid >> 6, h = tid & 63;
            float4 s = P8(0,k,h);
            #pragma unroll
            for (int i = 1; i < 8; i++) {
                float4 p = P8(i,k,h);
                s.x += p.x; s.y += p.y; s.z += p.z; s.w += p.w;
            }
            float4 qb = ((const float4*)Qb)[h];
            float  w  = ws[k];
            float4 r;
            r.x = leaky(s.x + qb.x) * w;
            r.y = leaky(s.y + qb.y) * w;
            r.z = leaky(s.z + qb.z) * w;
            r.w = leaky(s.w + qb.w) * w;
            P8(0,k,h) = r;
        }
        __syncthreads();

        if (tid < 64) {
            float4 s0 = P8(0,0,tid), s1 = P8(0,1,tid);
            float4 s2 = P8(0,2,tid), s3 = P8(0,3,tid);
            float4 s;
            s.x = s0.x + s1.x + s2.x + s3.x;
            s.y = s0.y + s1.y + s2.y + s3.y;
            s.z = s0.z + s1.z + s2.z + s3.z;
            s.w = s0.w + s1.w + s2.w + s3.w;
            ((float4*)(g_partial + ((size_t)b * NCHUNKS + chunk) * HDIM))[tid] = s;
        }
        #undef P8
        if (tid == 0) {
            g_wsum[b * NCHUNKS + chunk] = ws[0] + ws[1] + ws[2] + ws[3];
        }
        __threadfence();
        __syncthreads();
        if (tid == 0) atomicAdd(&g_done, 1);

    } else {
        // ================= GEMV ROLE (R8 k2 + last-block norm) =================
        const int ob = bid - NCOMPUTE;   // 0..7, o-tile of 32

        float*  cs_s = (float*)smem_raw;                       // [8][CS_PAD] = 16.5 KB
        float4* red  = (float4*)(smem_raw + 8 * CS_PAD * 4);   // [16][64]    = 16 KB
        float*  sq   = (float*)(smem_raw + 8 * CS_PAD * 4 + 16384);  // [64]
        float*  dn   = (float*)(smem_raw + 8 * CS_PAD * 4 + 16640);  // [8]
        int*    s_fl = (int*)  (smem_raw + 8 * CS_PAD * 4 + 16672);

        // Pre-gate: node embeddings (independent of compute blocks) -> overlap
        if (tid < 512) {
            int bn = tid >> 6, col = tid & 63;
            float4 v = *(const float4*)(emb + ((size_t)(bn * NDIM + nid)) * CDIM + col * 4);
            *(float4*)(cs_s + bn * CS_PAD + col * 4) = v;
        }

        // Gate on compute completion
        if (tid == 0) {
            while (atomicAdd(&g_done, 0) < NCOMPUTE) __nanosleep(64);
        }
        __syncthreads();
        __threadfence();

        // Phase A remainder: reduce 16 chunk partials + denoms (cross-SM -> __ldcg)
        float s0 = 0.f, s1 = 0.f;
        {
            const int b0 = tid >> 8, h0 = tid & 255;
            const int b1 = b0 + 4;
            const float* gp0 = g_partial + ((size_t)b0 * NCHUNKS) * HDIM + h0;
            const float* gp1 = g_partial + ((size_t)b1 * NCHUNKS) * HDIM + h0;
            #pragma unroll
            for (int ch = 0; ch < NCHUNKS; ch++) {
                s0 += __ldcg(gp0 + ch * HDIM);
                s1 += __ldcg(gp1 + ch * HDIM);
            }
        }
        if (tid >= 512 && tid < 512 + BDIM) {
            const int bn = tid - 512;
            float d = 0.0f;
            #pragma unroll
            for (int i = 0; i < NCHUNKS; i++) d += __ldcg(&g_wsum[bn * NCHUNKS + i]);
            dn[bn] = d + EPS;
        }
        __syncthreads();
        {
            const int b0 = tid >> 8, h0 = tid & 255;
            const int b1 = b0 + 4;
            cs_s[b0 * CS_PAD + CDIM + h0] = s0 / dn[b0];
            cs_s[b1 * CS_PAD + CDIM + h0] = s1 / dn[b1];
        }
        __syncthreads();

        // Phase B: GEMV — o-tile for all 8 batches
        const int og = tid & 7;
        const int bb = (tid >> 3) & 7;
        const int cq = tid >> 6;
        const float4* Ww4 = (const float4*)Ww;
        const float*  e   = cs_s + bb * CS_PAD;

        float4 acc = make_float4(0.f,0.f,0.f,0.f);
        #pragma unroll 8
        for (int c = cq * 32; c < cq * 32 + 32; c++) {
            float  ev = e[c];
            float4 q  = __ldg(&Ww4[c * 64 + ob * 8 + og]);
            acc.x = fmaf(ev, q.x, acc.x);
            acc.y = fmaf(ev, q.y, acc.y);
            acc.z = fmaf(ev, q.z, acc.z);
            acc.w = fmaf(ev, q.w, acc.w);
        }
        red[cq * 64 + bb * 8 + og] = acc;
        __syncthreads();

        if (tid < 64) {
            const int b2 = tid >> 3, og2 = tid & 7;
            float4 s = red[tid];
            #pragma unroll
            for (int i = 1; i < 16; i++) {
                float4 rr = red[i * 64 + tid];
                s.x += rr.x; s.y += rr.y; s.z += rr.z; s.w += rr.w;
            }
            float4 wb = ((const float4*)Wb)[ob * 8 + og2];
            float4 v;
            v.x = leaky(s.x + wb.x);
            v.y = leaky(s.y + wb.y);
            v.z = leaky(s.z + wb.z);
            v.w = leaky(s.w + wb.w);
            *(float4*)(g_hidden + (size_t)b2 * ODIM + ob * 32 + og2 * 4) = v;
            sq[tid] = v.x*v.x + v.y*v.y + v.z*v.z + v.w*v.w;
        }
        __syncthreads();
        if (tid < 8) {
            float t = 0.f;
            #pragma unroll
            for (int i = 0; i < 8; i++) t += sq[tid * 8 + i];
            g_ssq[tid * NGEMV + ob] = t;
        }
        __threadfence();
        __syncthreads();
        if (tid == 0) *s_fl = (atomicAdd(&g_arrive, 1) == NGEMV - 1);
        __syncthreads();

        if (*s_fl) {
            // Last-arriving gemv block: normalize + store + reset counters.
            __threadfence();
            if (tid < 8) {
                float t = 0.f;
                #pragma unroll
                for (int i = 0; i < 8; i++) t += __ldcg(&g_ssq[tid * NGEMV + i]);
                s_misc[tid] = 1.0f / (sqrtf(t) + EPS);
            }
            __syncthreads();
            if (tid < 512) {
                int bn = tid >> 6, o4 = tid & 63;
                float4 v = __ldcg(((const float4*)(g_hidden + (size_t)bn * ODIM)) + o4);
                float iv = s_misc[bn];
                v.x *= iv; v.y *= iv; v.z *= iv; v.w *= iv;
                *(float4*)(out + (size_t)bn * ODIM + o4 * 4) = v;
            }
            if (tid == 0) { g_done = 0; g_arrive = 0; }
        }
    }
}

extern "C" void kernel_launch(void* const* d_in, const int* in_sizes, int n_in,
                              void* d_out, int out_size)
{
    (void)in_sizes; (void)n_in; (void)out_size;
    const float* emb     = (const float*)d_in[0];
    const float* weights = (const float*)d_in[1];
    const float* Qw      = (const float*)d_in[2];
    const float* Qb      = (const float*)d_in[3];
    const float* Ww      = (const float*)d_in[4];
    const float* Wb      = (const float*)d_in[5];
    const int*   nb      = (const int*)d_in[6];
    const int*   nid     = (const int*)d_in[7];
    float*       out     = (float*)d_out;

    fused_convolve<<<NCOMPUTE + NGEMV, 1024>>>(emb, weights, Qw, Qb, Ww, Wb, nb, nid, out);
}